// round 11
// baseline (speedup 1.0000x reference)
#include <cuda_runtime.h>
#include <mma.h>
#include <math.h>

using namespace nvcuda;

#define BD 2
#define TT 2048
#define CC 1024
#define HH 16
#define HD 64

// Scratch (no cudaMalloc allowed)
__device__ float g_qkv[(size_t)BD * TT * 3 * CC];   // [B,T,3C]
__device__ float g_att[(size_t)BD * TT * CC];       // [B,T,C]
__device__ float g_d[3 * TT];                        // polynomial coeffs D1,D2,D3

typedef wmma::fragment<wmma::matrix_a, 16, 16, 8, wmma::precision::tf32, wmma::row_major> FragA;
typedef wmma::fragment<wmma::matrix_b, 16, 16, 8, wmma::precision::tf32, wmma::row_major> FragBR;
typedef wmma::fragment<wmma::matrix_b, 16, 16, 8, wmma::precision::tf32, wmma::col_major> FragBC;
typedef wmma::fragment<wmma::accumulator, 16, 16, 8, float> FragC;

__device__ __forceinline__ void cvt_tf32(float* x, int n) {
#pragma unroll
    for (int i = 0; i < n; i++) x[i] = wmma::__float_to_tf32(x[i]);
}

// 0.5*cos(x)+0.5 ~ 1 + x2*(-1/4 + x2*(1/48 - x2/1440)); |x| small
__device__ __forceinline__ float cosmask(float x) {
    float x2 = x * x;
    return fmaf(x2, fmaf(x2, fmaf(x2, -6.9444444e-4f, 2.0833333e-2f), -0.25f), 1.0f);
}

// ---------------------------------------------------------------------------
// TF32 GEMM: C = A @ B row-major. BM=BN=128, BK=32, 8 warps. (unchanged)
// ---------------------------------------------------------------------------
#define GALD 36
#define GBLD 136

__global__ void __launch_bounds__(256, 2) gemm_tf32(
    const float* __restrict__ A, const float* __restrict__ B,
    float* __restrict__ C, int M, int N, int K)
{
    __shared__ float As[128 * GALD];
    __shared__ float Bs[32 * GBLD];

    const int tid = threadIdx.x;
    const int w = tid >> 5;
    const int wm = w & 3;
    const int wn = w >> 2;
    const int bx = blockIdx.x;
    const int by = blockIdx.y;

    const float* Ab = A + (size_t)by * 128 * K;
    const float* Bb = B + (size_t)bx * 128;

    FragC acc[2][4];
#pragma unroll
    for (int i = 0; i < 2; i++)
#pragma unroll
        for (int j = 0; j < 4; j++) wmma::fill_fragment(acc[i][j], 0.f);

    for (int kt = 0; kt < K; kt += 32) {
#pragma unroll
        for (int i = 0; i < 4; i++) {
            int idx = tid + i * 256;
            int r = idx >> 3;
            int c = (idx & 7) << 2;
            *(float4*)&As[r * GALD + c] = *(const float4*)(Ab + (size_t)r * K + kt + c);
        }
#pragma unroll
        for (int i = 0; i < 4; i++) {
            int idx = tid + i * 256;
            int r = idx >> 5;
            int c = (idx & 31) << 2;
            *(float4*)&Bs[r * GBLD + c] = *(const float4*)(Bb + (size_t)(kt + r) * N + c);
        }
        __syncthreads();

#pragma unroll
        for (int ks = 0; ks < 32; ks += 8) {
            FragA af[2];
            FragBR bf[4];
#pragma unroll
            for (int i = 0; i < 2; i++) {
                wmma::load_matrix_sync(af[i], &As[(wm * 32 + i * 16) * GALD + ks], GALD);
                cvt_tf32(af[i].x, af[i].num_elements);
            }
#pragma unroll
            for (int j = 0; j < 4; j++) {
                wmma::load_matrix_sync(bf[j], &Bs[ks * GBLD + wn * 64 + j * 16], GBLD);
                cvt_tf32(bf[j].x, bf[j].num_elements);
            }
#pragma unroll
            for (int i = 0; i < 2; i++)
#pragma unroll
                for (int j = 0; j < 4; j++)
                    wmma::mma_sync(acc[i][j], af[i], bf[j], acc[i][j]);
        }
        __syncthreads();
    }

#pragma unroll
    for (int i = 0; i < 2; i++)
#pragma unroll
        for (int j = 0; j < 4; j++) {
            float* Cp = C + (size_t)(by * 128 + wm * 32 + i * 16) * N
                          + bx * 128 + wn * 64 + j * 16;
            wmma::store_matrix_sync(Cp, acc[i][j], N, wmma::mem_row_major);
        }
}

// ---------------------------------------------------------------------------
// Output learned mask (float4, in place)
// ---------------------------------------------------------------------------
__global__ void mask_kernel(float4* __restrict__ out,
                            const float* __restrict__ A2,
                            const float* __restrict__ B2, int total4)
{
    int idx = blockIdx.x * 256 + threadIdx.x;
    if (idx >= total4) return;
    int col = (idx & (CC / 4 - 1)) << 2;
    float4 v = out[idx];
    v.x *= cosmask(fmaf(A2[col + 0], v.x, B2[col + 0]));
    v.y *= cosmask(fmaf(A2[col + 1], v.y, B2[col + 1]));
    v.z *= cosmask(fmaf(A2[col + 2], v.z, B2[col + 2]));
    v.w *= cosmask(fmaf(A2[col + 3], v.w, B2[col + 3]));
    out[idx] = v;
}

// ---------------------------------------------------------------------------
// Precompute polynomial coefficients for the attention learned mask:
// p*mask(p) ~ D1*p + D2*p^2 + D3*p^3
// D1 = 0.5+0.5cosB, D2 = -0.5*A*sinB, D3 = -0.25*A^2*cosB
// ---------------------------------------------------------------------------
__global__ void coef_kernel(const float* __restrict__ A1,
                            const float* __restrict__ B1, float* __restrict__ D)
{
    int i = blockIdx.x * 256 + threadIdx.x;
    if (i >= TT) return;
    float a = A1[i], b = B1[i];
    float sb, cb;
    __sincosf(b, &sb, &cb);
    D[i]          = 0.5f + 0.5f * cb;
    D[TT + i]     = -0.5f * a * sb;
    D[2 * TT + i] = -0.25f * a * a * cb;
}

// ---------------------------------------------------------------------------
// Fused one-pass attention. CTA = (64 queries, head, batch), 256 thr = 8 warps.
// Per 64-key tile: S = (Q/8)K^T (wmma) -> e=exp(s) in fragments -> smem Ps
// -> row sums (regs) + 3 PV MMAs: O_m += (e^m) @ (D_m(k)*V).
// End: O = O1/l + O2/l^2 + O3/l^3 (staged via smem for row scaling).
// Smem: Qs,Ks,Vs1..3,Ps each 64x68 = 104.4KB total, 2 CTAs/SM.
// ---------------------------------------------------------------------------
#define ALD 68
#define AOFF_Q  0
#define AOFF_K  (64 * ALD)
#define AOFF_V1 (2 * 64 * ALD)
#define AOFF_V2 (3 * 64 * ALD)
#define AOFF_V3 (4 * 64 * ALD)
#define AOFF_P  (5 * 64 * ALD)
#define ASMEM   (6 * 64 * ALD)

__global__ void __launch_bounds__(256, 2) attn_fused(
    const float* __restrict__ qkv, const float* __restrict__ D,
    float* __restrict__ att)
{
    extern __shared__ float sm[];
    float* Qs  = sm + AOFF_Q;
    float* Ks  = sm + AOFF_K;
    float* Vs1 = sm + AOFF_V1;
    float* Vs2 = sm + AOFF_V2;
    float* Vs3 = sm + AOFF_V3;
    float* Ps  = sm + AOFF_P;

    const int tid = threadIdx.x;
    const int w = tid >> 5;
    const int wm = w & 3;      // 16-row strip of the 64-row tile
    const int wn = w >> 2;     // 32-col strip
    const int qt = (gridDim.x - 1) - blockIdx.x;   // heavy CTAs first
    const int h = blockIdx.y;
    const int b = blockIdx.z;
    const int qBase = qt * 64;
    const size_t bOff = (size_t)b * TT * 3 * CC;
    const int ldq = 3 * CC;
    const int hOff = h * HD;
    const int nT = qt + 1;

    const int row = tid >> 2;          // 0..63 scalar-phase row
    const int sub = tid & 3;           // 16 cols each
    const float* D1 = D;
    const float* D2 = D + TT;
    const float* D3 = D + 2 * TT;

    // Q tile [64][64] scaled by 1/8
#pragma unroll
    for (int i = 0; i < 4; i++) {
        int idx = tid + i * 256;
        int r = idx >> 4;
        int c = (idx & 15) << 2;
        float4 v = *(const float4*)(qkv + bOff + (size_t)(qBase + r) * ldq + hOff + c);
        float* dst = &Qs[r * ALD + c];
        dst[0] = v.x * 0.125f; dst[1] = v.y * 0.125f;
        dst[2] = v.z * 0.125f; dst[3] = v.w * 0.125f;
    }

    float lacc = 0.f;
    FragC oacc[3][2];
#pragma unroll
    for (int m = 0; m < 3; m++)
#pragma unroll
        for (int t = 0; t < 2; t++) wmma::fill_fragment(oacc[m][t], 0.f);

    for (int kt = 0; kt < nT; kt++) {
        const int kBase = kt * 64;
        const bool diag = (kt == qt);
        // load K and V (V scaled into 3 coefficient variants)
#pragma unroll
        for (int i = 0; i < 4; i++) {
            int idx = tid + i * 256;
            int r = idx >> 4;
            int c = (idx & 15) << 2;
            const float* src = qkv + bOff + (size_t)(kBase + r) * ldq + hOff + c;
            *(float4*)&Ks[r * ALD + c] = *(const float4*)(src + CC);
            float4 v = *(const float4*)(src + 2 * CC);
            int k = kBase + r;
            float d1 = __ldg(D1 + k), d2 = __ldg(D2 + k), d3 = __ldg(D3 + k);
            float* p1 = &Vs1[r * ALD + c];
            float* p2 = &Vs2[r * ALD + c];
            float* p3 = &Vs3[r * ALD + c];
            p1[0] = d1 * v.x; p1[1] = d1 * v.y; p1[2] = d1 * v.z; p1[3] = d1 * v.w;
            p2[0] = d2 * v.x; p2[1] = d2 * v.y; p2[2] = d2 * v.z; p2[3] = d2 * v.w;
            p3[0] = d3 * v.x; p3[1] = d3 * v.y; p3[2] = d3 * v.z; p3[3] = d3 * v.w;
        }
        __syncthreads();

        // S = Q K^T for the 64x64 tile; each warp 16x32 (1x2 frags)
        {
            FragC sacc[2];
            wmma::fill_fragment(sacc[0], 0.f);
            wmma::fill_fragment(sacc[1], 0.f);
#pragma unroll
            for (int ks = 0; ks < 64; ks += 8) {
                FragA af;
                wmma::load_matrix_sync(af, &Qs[(wm * 16) * ALD + ks], ALD);
                cvt_tf32(af.x, af.num_elements);
#pragma unroll
                for (int j = 0; j < 2; j++) {
                    FragBC bf;
                    wmma::load_matrix_sync(bf, &Ks[(wn * 32 + j * 16) * ALD + ks], ALD);
                    cvt_tf32(bf.x, bf.num_elements);
                    wmma::mma_sync(sacc[j], af, bf, sacc[j]);
                }
            }
            // e = exp(s) in fragments (clamped), store to Ps
#pragma unroll
            for (int j = 0; j < 2; j++) {
#pragma unroll
                for (int e = 0; e < sacc[j].num_elements; e++)
                    sacc[j].x[e] = __expf(fminf(sacc[j].x[e], 20.f));
                wmma::store_matrix_sync(&Ps[(wm * 16) * ALD + wn * 32 + j * 16],
                                        sacc[j], ALD, wmma::mem_row_major);
            }
        }
        __syncthreads();

        // scalar: causal zero (diag only) + row-sum accumulation
        if (diag) {
#pragma unroll
            for (int j4 = 0; j4 < 4; j4++) {
                int c0 = sub * 16 + j4 * 4;
                float4 e4 = *(const float4*)&Ps[row * ALD + c0];
                if (c0 + 0 > row) e4.x = 0.f;
                if (c0 + 1 > row) e4.y = 0.f;
                if (c0 + 2 > row) e4.z = 0.f;
                if (c0 + 3 > row) e4.w = 0.f;
                *(float4*)&Ps[row * ALD + c0] = e4;
                lacc += (e4.x + e4.y) + (e4.z + e4.w);
            }
            __syncthreads();   // zeros visible before PV reads
        } else {
#pragma unroll
            for (int j4 = 0; j4 < 4; j4++) {
                int c0 = sub * 16 + j4 * 4;
                float4 e4 = *(const float4*)&Ps[row * ALD + c0];
                lacc += (e4.x + e4.y) + (e4.z + e4.w);
            }
        }

        // PV: O_m += (e^m) @ Vs_m ; A-load shared across m (register powers)
#pragma unroll
        for (int ks = 0; ks < 64; ks += 8) {
            FragA af1, af2, af3;
            wmma::load_matrix_sync(af1, &Ps[(wm * 16) * ALD + ks], ALD);
#pragma unroll
            for (int e = 0; e < af1.num_elements; e++) {
                float ev = af1.x[e];
                float ev2 = ev * ev;
                af2.x[e] = wmma::__float_to_tf32(ev2);
                af3.x[e] = wmma::__float_to_tf32(ev2 * ev);
                af1.x[e] = wmma::__float_to_tf32(ev);
            }
#pragma unroll
            for (int t = 0; t < 2; t++) {
                FragBR bf;
                wmma::load_matrix_sync(bf, &Vs1[ks * ALD + wn * 32 + t * 16], ALD);
                cvt_tf32(bf.x, bf.num_elements);
                wmma::mma_sync(oacc[0][t], af1, bf, oacc[0][t]);
                wmma::load_matrix_sync(bf, &Vs2[ks * ALD + wn * 32 + t * 16], ALD);
                cvt_tf32(bf.x, bf.num_elements);
                wmma::mma_sync(oacc[1][t], af2, bf, oacc[1][t]);
                wmma::load_matrix_sync(bf, &Vs3[ks * ALD + wn * 32 + t * 16], ALD);
                cvt_tf32(bf.x, bf.num_elements);
                wmma::mma_sync(oacc[2][t], af3, bf, oacc[2][t]);
            }
        }
        __syncthreads();   // done with Ks/Vs/Ps before next tile load
    }

    // reduce row sums across the 4 threads of each row (same warp)
    lacc += __shfl_xor_sync(0xffffffffu, lacc, 1);
    lacc += __shfl_xor_sync(0xffffffffu, lacc, 2);
    const float rl = 1.f / lacc;
    const float rl2 = rl * rl;
    const float rl3 = rl2 * rl;

    // stage O_m into Vs buffers (free now), then row-scaled combine
#pragma unroll
    for (int t = 0; t < 2; t++) {
        wmma::store_matrix_sync(&Vs1[(wm * 16) * ALD + wn * 32 + t * 16], oacc[0][t],
                                ALD, wmma::mem_row_major);
        wmma::store_matrix_sync(&Vs2[(wm * 16) * ALD + wn * 32 + t * 16], oacc[1][t],
                                ALD, wmma::mem_row_major);
        wmma::store_matrix_sync(&Vs3[(wm * 16) * ALD + wn * 32 + t * 16], oacc[2][t],
                                ALD, wmma::mem_row_major);
    }
    __syncthreads();

    const size_t oBase = (size_t)b * TT * CC + (size_t)qBase * CC + hOff;
#pragma unroll
    for (int j4 = 0; j4 < 4; j4++) {
        int c0 = sub * 16 + j4 * 4;
        float4 o1 = *(const float4*)&Vs1[row * ALD + c0];
        float4 o2 = *(const float4*)&Vs2[row * ALD + c0];
        float4 o3 = *(const float4*)&Vs3[row * ALD + c0];
        float4 o;
        o.x = fmaf(o1.x, rl, fmaf(o2.x, rl2, o3.x * rl3));
        o.y = fmaf(o1.y, rl, fmaf(o2.y, rl2, o3.y * rl3));
        o.z = fmaf(o1.z, rl, fmaf(o2.z, rl2, o3.z * rl3));
        o.w = fmaf(o1.w, rl, fmaf(o2.w, rl2, o3.w * rl3));
        *(float4*)(att + oBase + (size_t)row * CC + c0) = o;
    }
}

// ---------------------------------------------------------------------------
extern "C" void kernel_launch(void* const* d_in, const int* in_sizes, int n_in,
                              void* d_out, int out_size)
{
    const float* x     = (const float*)d_in[0];
    const float* Wqkv  = (const float*)d_in[1];
    const float* Wproj = (const float*)d_in[2];
    const float* A1    = (const float*)d_in[3];
    const float* B1    = (const float*)d_in[4];
    const float* A2    = (const float*)d_in[5];
    const float* B2    = (const float*)d_in[6];
    float* out = (float*)d_out;

    float *qkv, *att, *Dc;
    cudaGetSymbolAddress((void**)&qkv, g_qkv);
    cudaGetSymbolAddress((void**)&att, g_att);
    cudaGetSymbolAddress((void**)&Dc, g_d);

    // 1) QKV projection
    {
        dim3 grid(3 * CC / 128, (BD * TT) / 128);
        gemm_tf32<<<grid, 256>>>(x, Wqkv, qkv, BD * TT, 3 * CC, CC);
    }
    // 2) mask polynomial coefficients
    coef_kernel<<<(TT + 255) / 256, 256>>>(A1, B1, Dc);
    // 3) fused one-pass attention
    {
        size_t smem = ASMEM * sizeof(float);
        cudaFuncSetAttribute(attn_fused, cudaFuncAttributeMaxDynamicSharedMemorySize,
                             (int)smem);
        dim3 grid(TT / 64, HH, BD);
        attn_fused<<<grid, 256, smem>>>(qkv, Dc, att);
    }
    // 4) output projection
    {
        dim3 grid(CC / 128, (BD * TT) / 128);
        gemm_tf32<<<grid, 256>>>(att, Wproj, out, BD * TT, CC, CC);
    }
    // 5) output learned mask
    {
        int total4 = BD * TT * CC / 4;
        mask_kernel<<<(total4 + 255) / 256, 256>>>((float4*)out, A2, B2, total4);
    }
}

// round 12
// speedup vs baseline: 1.3246x; 1.3246x over previous
#include <cuda_runtime.h>
#include <mma.h>
#include <math.h>

using namespace nvcuda;

#define BD 2
#define TT 2048
#define CC 1024
#define HH 16
#define HD 64

// Scratch (no cudaMalloc allowed)
__device__ float g_qkv[(size_t)BD * TT * 3 * CC];   // [B,T,3C]
__device__ float g_att[(size_t)BD * TT * CC];       // [B,T,C]
__device__ float g_e[(size_t)BD * HH * TT * TT];    // E = exp(S) scratch
__device__ float g_l[(size_t)BD * HH * TT];         // 1/rowsum

typedef wmma::fragment<wmma::matrix_a, 16, 16, 8, wmma::precision::tf32, wmma::row_major> FragA;
typedef wmma::fragment<wmma::matrix_b, 16, 16, 8, wmma::precision::tf32, wmma::row_major> FragBR;
typedef wmma::fragment<wmma::matrix_b, 16, 16, 8, wmma::precision::tf32, wmma::col_major> FragBC;
typedef wmma::fragment<wmma::accumulator, 16, 16, 8, float> FragC;

__device__ __forceinline__ void cvt_tf32(float* x, int n) {
#pragma unroll
    for (int i = 0; i < n; i++) x[i] = wmma::__float_to_tf32(x[i]);
}

// 0.5*cos(x)+0.5 = 1 + x2*(-1/4 + x2*(1/48 - x2/1440)); |x| small here
__device__ __forceinline__ float cosmask(float x) {
    float x2 = x * x;
    return fmaf(x2, fmaf(x2, fmaf(x2, -6.9444444e-4f, 2.0833333e-2f), -0.25f), 1.0f);
}

__device__ __forceinline__ void cp_async16(void* smem, const void* gmem) {
    unsigned saddr = (unsigned)__cvta_generic_to_shared(smem);
    asm volatile("cp.async.cg.shared.global [%0], [%1], 16;\n" :: "r"(saddr), "l"(gmem));
}
__device__ __forceinline__ void cp_commit() {
    asm volatile("cp.async.commit_group;\n");
}
template <int N>
__device__ __forceinline__ void cp_wait() {
    asm volatile("cp.async.wait_group %0;\n" :: "n"(N));
}

// ---------------------------------------------------------------------------
// Pipelined TF32 GEMM: C[M,N] = A[M,K] @ B[K,N] row-major.
// BM=BN=128, BK=32, 3-stage cp.async pipeline, 8 warps, warp tile 32x64.
// Dynamic smem: 3 * (128*36 + 32*132) * 4 = 105.8 KB, 2 CTAs/SM.
// ---------------------------------------------------------------------------
#define GALD 36      // A stage row pad (32+4)
#define GBLD 132     // B stage row pad (128+4), 16B-aligned rows
#define GA_STAGE (128 * GALD)              // 4608 floats
#define GB_STAGE (32 * GBLD)               // 4224 floats
#define GSTAGE (GA_STAGE + GB_STAGE)       // 8832 floats
#define GSTAGES 3
#define GSMEM_BYTES (GSTAGES * GSTAGE * sizeof(float))

__global__ void __launch_bounds__(256, 2) gemm_tf32_pipe(
    const float* __restrict__ A, const float* __restrict__ B,
    float* __restrict__ C, int M, int N, int K)
{
    extern __shared__ float smp[];

    const int tid = threadIdx.x;
    const int w = tid >> 5;
    const int wm = w & 3;        // 32-row strip
    const int wn = w >> 2;       // 64-col strip
    const int bx = blockIdx.x;
    const int by = blockIdx.y;

    const float* Ab = A + (size_t)by * 128 * K;
    const float* Bb = B + (size_t)bx * 128;

    const int nK = K >> 5;       // K/32 stages of work

    // per-thread load map (4 x 16B chunks each for A and B per stage)
    const int aRow = tid >> 3;          // base rows 0..31 (i adds 32)
    const int aCol = (tid & 7) << 2;
    const int bRow = tid >> 5;          // base rows 0..7 (i adds 8)
    const int bCol = (tid & 31) << 2;

    auto loadStage = [&](int s, int kt) {
        float* As = smp + s * GSTAGE;
        float* Bs = As + GA_STAGE;
#pragma unroll
        for (int i = 0; i < 4; i++) {
            int r = aRow + i * 32;
            cp_async16(&As[r * GALD + aCol], Ab + (size_t)r * K + kt + aCol);
        }
#pragma unroll
        for (int i = 0; i < 4; i++) {
            int r = bRow + i * 8;
            cp_async16(&Bs[r * GBLD + bCol], Bb + (size_t)(kt + r) * N + bCol);
        }
        cp_commit();
    };

    FragC acc[2][4];
#pragma unroll
    for (int i = 0; i < 2; i++)
#pragma unroll
        for (int j = 0; j < 4; j++) wmma::fill_fragment(acc[i][j], 0.f);

    // prologue: prefetch stages 0,1
    loadStage(0, 0);
    loadStage(1, 32);

    for (int kt = 0; kt < nK; kt++) {
        cp_wait<GSTAGES - 2>();   // stage kt ready
        __syncthreads();          // all warps past compute(kt-1); stage kt visible

        // issue loads for stage kt+2 (buffer last computed at kt-1 -> safe)
        if (kt + 2 < nK) loadStage((kt + 2) % GSTAGES, (kt + 2) << 5);

        float* As = smp + (kt % GSTAGES) * GSTAGE;
        float* Bs = As + GA_STAGE;
#pragma unroll
        for (int ks = 0; ks < 32; ks += 8) {
            FragA af[2];
            FragBR bf[4];
#pragma unroll
            for (int i = 0; i < 2; i++) {
                wmma::load_matrix_sync(af[i], &As[(wm * 32 + i * 16) * GALD + ks], GALD);
                cvt_tf32(af[i].x, af[i].num_elements);
            }
#pragma unroll
            for (int j = 0; j < 4; j++) {
                wmma::load_matrix_sync(bf[j], &Bs[ks * GBLD + wn * 64 + j * 16], GBLD);
                cvt_tf32(bf[j].x, bf[j].num_elements);
            }
#pragma unroll
            for (int i = 0; i < 2; i++)
#pragma unroll
                for (int j = 0; j < 4; j++)
                    wmma::mma_sync(acc[i][j], af[i], bf[j], acc[i][j]);
        }
    }

#pragma unroll
    for (int i = 0; i < 2; i++)
#pragma unroll
        for (int j = 0; j < 4; j++) {
            float* Cp = C + (size_t)(by * 128 + wm * 32 + i * 16) * N
                          + bx * 128 + wn * 64 + j * 16;
            wmma::store_matrix_sync(Cp, acc[i][j], N, wmma::mem_row_major);
        }
}

// ---------------------------------------------------------------------------
// Output learned mask (float4, in place)
// ---------------------------------------------------------------------------
__global__ void mask_kernel(float4* __restrict__ out,
                            const float* __restrict__ A2,
                            const float* __restrict__ B2, int total4)
{
    int idx = blockIdx.x * 256 + threadIdx.x;
    if (idx >= total4) return;
    int col = (idx & (CC / 4 - 1)) << 2;
    float4 v = out[idx];
    v.x *= cosmask(fmaf(A2[col + 0], v.x, B2[col + 0]));
    v.y *= cosmask(fmaf(A2[col + 1], v.y, B2[col + 1]));
    v.z *= cosmask(fmaf(A2[col + 2], v.z, B2[col + 2]));
    v.w *= cosmask(fmaf(A2[col + 3], v.w, B2[col + 3]));
    out[idx] = v;
}

// ---------------------------------------------------------------------------
// S->E: one CTA per causal 128x128 tile. grid (136, H, B), 256 thr = 8 warps.
// (measured-best R7 version, unchanged)
// ---------------------------------------------------------------------------
#define ELD 68
#define ESLD 132
#define EOFF_Q 0
#define EOFF_SK (128 * ELD)
#define ESMEM (EOFF_SK + 128 * ESLD)

__global__ void __launch_bounds__(256, 2) s2e_kernel(
    const float* __restrict__ qkv, float* __restrict__ E)
{
    extern __shared__ float sm[];
    float* Qs = sm + EOFF_Q;
    float* SK = sm + EOFF_SK;     // K tile (ld ELD) during MMA; S tile (ld ESLD) after

    const int p = blockIdx.x;
    const int h = blockIdx.y;
    const int b = blockIdx.z;
    int qt = 0;
    while ((qt + 1) * (qt + 2) / 2 <= p) qt++;
    const int kt = p - qt * (qt + 1) / 2;

    const int tid = threadIdx.x;
    const int w = tid >> 5;
    const int wm = w & 3;
    const int wn = w >> 2;
    const size_t bOff = (size_t)b * TT * 3 * CC;
    const int ldq = 3 * CC;
    const int hOff = h * HD;
    const size_t eB = ((size_t)(b * HH + h) * TT + (size_t)qt * 128) * TT + (size_t)kt * 128;

#pragma unroll
    for (int i = 0; i < 8; i++) {
        int idx = tid + i * 256;
        int r = idx >> 4;
        int c = (idx & 15) << 2;
        float4 v = *(const float4*)(qkv + bOff + (size_t)(qt * 128 + r) * ldq + hOff + c);
        float* dst = &Qs[r * ELD + c];
        dst[0] = v.x * 0.125f; dst[1] = v.y * 0.125f;
        dst[2] = v.z * 0.125f; dst[3] = v.w * 0.125f;
        *(float4*)&SK[r * ELD + c] =
            *(const float4*)(qkv + bOff + (size_t)(kt * 128 + r) * ldq + CC + hOff + c);
    }
    __syncthreads();

    FragC sacc[2][4];
#pragma unroll
    for (int i = 0; i < 2; i++)
#pragma unroll
        for (int j = 0; j < 4; j++) wmma::fill_fragment(sacc[i][j], 0.f);

#pragma unroll
    for (int ks = 0; ks < 64; ks += 8) {
        FragA af[2];
        FragBC bf[4];
#pragma unroll
        for (int i = 0; i < 2; i++) {
            wmma::load_matrix_sync(af[i], &Qs[(wm * 32 + i * 16) * ELD + ks], ELD);
            cvt_tf32(af[i].x, af[i].num_elements);
        }
#pragma unroll
        for (int j = 0; j < 4; j++) {
            wmma::load_matrix_sync(bf[j], &SK[(wn * 64 + j * 16) * ELD + ks], ELD);
            cvt_tf32(bf[j].x, bf[j].num_elements);
        }
#pragma unroll
        for (int i = 0; i < 2; i++)
#pragma unroll
            for (int j = 0; j < 4; j++)
                wmma::mma_sync(sacc[i][j], af[i], bf[j], sacc[i][j]);
    }

    if (kt < qt) {
#pragma unroll
        for (int i = 0; i < 2; i++)
#pragma unroll
            for (int j = 0; j < 4; j++) {
#pragma unroll
                for (int e = 0; e < sacc[i][j].num_elements; e++)
                    sacc[i][j].x[e] = __expf(fminf(sacc[i][j].x[e], 60.f));
                wmma::store_matrix_sync(
                    E + eB + (size_t)(wm * 32 + i * 16) * TT + wn * 64 + j * 16,
                    sacc[i][j], TT, wmma::mem_row_major);
            }
    } else {
        __syncthreads();
#pragma unroll
        for (int i = 0; i < 2; i++)
#pragma unroll
            for (int j = 0; j < 4; j++)
                wmma::store_matrix_sync(&SK[(wm * 32 + i * 16) * ESLD + wn * 64 + j * 16],
                                        sacc[i][j], ESLD, wmma::mem_row_major);
        __syncthreads();
#pragma unroll
        for (int i = 0; i < 16; i++) {
            int r = (tid >> 5) + i * 8;
            int c = (tid & 31) << 2;
            float4 s4 = *(const float4*)&SK[r * ESLD + c];
            float4 e4;
            e4.x = (c + 0 <= r) ? __expf(fminf(s4.x, 60.f)) : 0.f;
            e4.y = (c + 1 <= r) ? __expf(fminf(s4.y, 60.f)) : 0.f;
            e4.z = (c + 2 <= r) ? __expf(fminf(s4.z, 60.f)) : 0.f;
            e4.w = (c + 3 <= r) ? __expf(fminf(s4.w, 60.f)) : 0.f;
            *(float4*)(E + eB + (size_t)r * TT + c) = e4;
        }
    }
}

// ---------------------------------------------------------------------------
// Row sums of E -> 1/l. One warp per row. (R7 version, unchanged)
// ---------------------------------------------------------------------------
__global__ void rowsum_kernel(const float* __restrict__ E, float* __restrict__ L)
{
    const int R = blockIdx.x * 8 + (threadIdx.x >> 5);
    const int lane = threadIdx.x & 31;
    const int r = R & (TT - 1);
    const int bh = R >> 11;
    const int len = ((r >> 7) + 1) << 7;
    const float* row = E + ((size_t)bh * TT + r) * TT;
    float s = 0.f;
    for (int k = lane * 4; k < len; k += 128) {
        float4 v = *(const float4*)(row + k);
        s += (v.x + v.y) + (v.z + v.w);
    }
#pragma unroll
    for (int o = 16; o > 0; o >>= 1) s += __shfl_xor_sync(0xffffffffu, s, o);
    if (lane == 0) L[R] = 1.f / s;
}

// ---------------------------------------------------------------------------
// PV: per (qt, h, b) CTA. O[128x64] = sum_kt P'(128x128) V(128x64).
// (R7 version, unchanged)
// ---------------------------------------------------------------------------
#define POFF_P 0
#define POFF_V (128 * ESLD)
#define POFF_L (POFF_V + 128 * ELD)
#define PSMEM (POFF_L + 128)

__global__ void __launch_bounds__(256, 2) pv_kernel(
    const float* __restrict__ qkv, const float* __restrict__ E,
    const float* __restrict__ L,
    const float* __restrict__ A1, const float* __restrict__ B1,
    float* __restrict__ att)
{
    extern __shared__ float sm[];
    float* Ps = sm + POFF_P;
    float* Vs = sm + POFF_V;
    float* ls = sm + POFF_L;

    const int tid = threadIdx.x;
    const int w = tid >> 5;
    const int wm = w & 3;
    const int wn = w >> 2;
    const int qt = (gridDim.x - 1) - blockIdx.x;   // heavy first
    const int h = blockIdx.y;
    const int b = blockIdx.z;
    const int bh = b * HH + h;
    const size_t bOff = (size_t)b * TT * 3 * CC;
    const int ldq = 3 * CC;
    const int hOff = h * HD;
    const size_t eQ = ((size_t)bh * TT + (size_t)qt * 128) * TT;

    if (tid < 128) ls[tid] = L[bh * TT + qt * 128 + tid];
    __syncthreads();

    FragC oacc[2][2];
#pragma unroll
    for (int i = 0; i < 2; i++)
#pragma unroll
        for (int t = 0; t < 2; t++) wmma::fill_fragment(oacc[i][t], 0.f);

    for (int kt = 0; kt <= qt; kt++) {
        const int kBase = kt * 128;
#pragma unroll
        for (int i = 0; i < 8; i++) {
            int idx = tid + i * 256;
            int r = idx >> 4;
            int c = (idx & 15) << 2;
            *(float4*)&Vs[r * ELD + c] =
                *(const float4*)(qkv + bOff + (size_t)(kBase + r) * ldq + 2 * CC + hOff + c);
        }
#pragma unroll
        for (int i = 0; i < 16; i++) {
            int r = (tid >> 5) + i * 8;
            int c = (tid & 31) << 2;
            float4 e4 = *(const float4*)(E + eQ + (size_t)r * TT + kBase + c);
            float rl = ls[r];
            int k0 = kBase + c;
            float4 p4;
            p4.x = e4.x * rl; p4.y = e4.y * rl;
            p4.z = e4.z * rl; p4.w = e4.w * rl;
            p4.x *= cosmask(fmaf(__ldg(A1 + k0 + 0), p4.x, __ldg(B1 + k0 + 0)));
            p4.y *= cosmask(fmaf(__ldg(A1 + k0 + 1), p4.y, __ldg(B1 + k0 + 1)));
            p4.z *= cosmask(fmaf(__ldg(A1 + k0 + 2), p4.z, __ldg(B1 + k0 + 2)));
            p4.w *= cosmask(fmaf(__ldg(A1 + k0 + 3), p4.w, __ldg(B1 + k0 + 3)));
            *(float4*)&Ps[r * ESLD + c] = p4;
        }
        __syncthreads();

#pragma unroll
        for (int ks = 0; ks < 128; ks += 8) {
            FragA af[2];
#pragma unroll
            for (int i = 0; i < 2; i++) {
                wmma::load_matrix_sync(af[i], &Ps[(wm * 32 + i * 16) * ESLD + ks], ESLD);
                cvt_tf32(af[i].x, af[i].num_elements);
            }
#pragma unroll
            for (int t = 0; t < 2; t++) {
                FragBR bf;
                wmma::load_matrix_sync(bf, &Vs[ks * ELD + wn * 32 + t * 16], ELD);
                cvt_tf32(bf.x, bf.num_elements);
#pragma unroll
                for (int i = 0; i < 2; i++)
                    wmma::mma_sync(oacc[i][t], af[i], bf, oacc[i][t]);
            }
        }
        __syncthreads();
    }

    const size_t oBase = (size_t)b * TT * CC;
#pragma unroll
    for (int i = 0; i < 2; i++)
#pragma unroll
        for (int t = 0; t < 2; t++) {
            float* Op = att + oBase + (size_t)(qt * 128 + wm * 32 + i * 16) * CC
                         + hOff + wn * 32 + t * 16;
            wmma::store_matrix_sync(Op, oacc[i][t], CC, wmma::mem_row_major);
        }
}

// ---------------------------------------------------------------------------
extern "C" void kernel_launch(void* const* d_in, const int* in_sizes, int n_in,
                              void* d_out, int out_size)
{
    const float* x     = (const float*)d_in[0];
    const float* Wqkv  = (const float*)d_in[1];
    const float* Wproj = (const float*)d_in[2];
    const float* A1    = (const float*)d_in[3];
    const float* B1    = (const float*)d_in[4];
    const float* A2    = (const float*)d_in[5];
    const float* B2    = (const float*)d_in[6];
    float* out = (float*)d_out;

    float *qkv, *att, *E, *L;
    cudaGetSymbolAddress((void**)&qkv, g_qkv);
    cudaGetSymbolAddress((void**)&att, g_att);
    cudaGetSymbolAddress((void**)&E, g_e);
    cudaGetSymbolAddress((void**)&L, g_l);

    cudaFuncSetAttribute(gemm_tf32_pipe, cudaFuncAttributeMaxDynamicSharedMemorySize,
                         (int)GSMEM_BYTES);

    // 1) QKV projection: [4096,1024] @ [1024,3072]
    {
        dim3 grid(3 * CC / 128, (BD * TT) / 128);
        gemm_tf32_pipe<<<grid, 256, GSMEM_BYTES>>>(x, Wqkv, qkv, BD * TT, 3 * CC, CC);
    }
    // 2a) S -> E (all causal tiles, fully parallel)
    {
        size_t smem = ESMEM * sizeof(float);
        cudaFuncSetAttribute(s2e_kernel, cudaFuncAttributeMaxDynamicSharedMemorySize,
                             (int)smem);
        dim3 grid(136, HH, BD);
        s2e_kernel<<<grid, 256, smem>>>(qkv, E);
    }
    // 2b) row sums -> 1/l
    {
        rowsum_kernel<<<BD * HH * TT / 8, 256>>>(E, L);
    }
    // 2c) O = P' V
    {
        size_t smem = PSMEM * sizeof(float);
        cudaFuncSetAttribute(pv_kernel, cudaFuncAttributeMaxDynamicSharedMemorySize,
                             (int)smem);
        dim3 grid(TT / 128, HH, BD);
        pv_kernel<<<grid, 256, smem>>>(qkv, E, L, A1, B1, att);
    }
    // 3) output projection: [4096,1024] @ [1024,1024]
    {
        dim3 grid(CC / 128, (BD * TT) / 128);
        gemm_tf32_pipe<<<grid, 256, GSMEM_BYTES>>>(att, Wproj, out, BD * TT, CC, CC);
    }
    // 4) output learned mask
    {
        int total4 = BD * TT * CC / 4;
        mask_kernel<<<(total4 + 255) / 256, 256>>>((float4*)out, A2, B2, total4);
    }
}

// round 13
// speedup vs baseline: 3.5947x; 2.7137x over previous
#include <cuda_runtime.h>
#include <cuda_fp16.h>
#include <mma.h>
#include <math.h>

using namespace nvcuda;

#define BD 2
#define TT 2048
#define CC 1024
#define HH 16
#define HD 64

// Scratch (no cudaMalloc allowed)
__device__ __half g_xh[(size_t)BD * TT * CC];
__device__ __half g_wqkvh[(size_t)CC * 3 * CC];      // Q columns pre-scaled by 1/8
__device__ __half g_wprojh[(size_t)CC * CC];
__device__ __half g_qkvh[(size_t)BD * TT * 3 * CC];  // [B,T,3C], q already /8
__device__ __half g_atth[(size_t)BD * TT * CC];
__device__ float  g_e[(size_t)BD * HH * TT * TT];    // E = exp(S), fp32
__device__ float  g_l[(size_t)BD * HH * TT];         // 1/rowsum

typedef wmma::fragment<wmma::matrix_a, 16, 16, 16, __half, wmma::row_major> HA;
typedef wmma::fragment<wmma::matrix_b, 16, 16, 16, __half, wmma::row_major> HBR;
typedef wmma::fragment<wmma::matrix_b, 16, 16, 16, __half, wmma::col_major> HBC;
typedef wmma::fragment<wmma::accumulator, 16, 16, 16, float> HC;

// 0.5*cos(x)+0.5 = 1 + x2*(-1/4 + x2*(1/48 - x2/1440)); |x| small here
__device__ __forceinline__ float cosmask(float x) {
    float x2 = x * x;
    return fmaf(x2, fmaf(x2, fmaf(x2, -6.9444444e-4f, 2.0833333e-2f), -0.25f), 1.0f);
}

__device__ __forceinline__ void cp_async16(void* smem, const void* gmem) {
    unsigned saddr = (unsigned)__cvta_generic_to_shared(smem);
    asm volatile("cp.async.cg.shared.global [%0], [%1], 16;\n" :: "r"(saddr), "l"(gmem));
}
__device__ __forceinline__ void cp_commit() {
    asm volatile("cp.async.commit_group;\n");
}
template <int N>
__device__ __forceinline__ void cp_wait() {
    asm volatile("cp.async.wait_group %0;\n" :: "n"(N));
}

// ---------------------------------------------------------------------------
// fp32 -> fp16 converters
// ---------------------------------------------------------------------------
__global__ void f2h_kernel(__half* __restrict__ dst, const float* __restrict__ src, int n4)
{
    int i = blockIdx.x * 256 + threadIdx.x;
    if (i >= n4) return;
    float4 v = ((const float4*)src)[i];
    ((__half2*)dst)[i * 2 + 0] = __floats2half2_rn(v.x, v.y);
    ((__half2*)dst)[i * 2 + 1] = __floats2half2_rn(v.z, v.w);
}

// Wqkv with Q-columns (col < CC) pre-scaled by 1/8
__global__ void wqkv_cvt_kernel(__half* __restrict__ dst, const float* __restrict__ src)
{
    int i = blockIdx.x * 256 + threadIdx.x;   // n4 = CC*3*CC/4, exact grid
    float4 v = ((const float4*)src)[i];
    int col = (i * 4) % (3 * CC);
    float s = (col < CC) ? 0.125f : 1.f;
    ((__half2*)dst)[i * 2 + 0] = __floats2half2_rn(v.x * s, v.y * s);
    ((__half2*)dst)[i * 2 + 1] = __floats2half2_rn(v.z * s, v.w * s);
}

// ---------------------------------------------------------------------------
// fp16 GEMM, fp32 accum: C[M,N] = A[M,K] @ B[K,N]. BM=BN=128, BK=32,
// 3-stage cp.async pipeline, 8 warps, warp tile 32x64.
// Epilogue stages through smem (reused pipeline buffers) -> half or float out.
// ---------------------------------------------------------------------------
#define GALDH 40      // A pad (32+8 halves)
#define GBLDH 136     // B pad (128+8 halves)
#define GA_ST (128 * GALDH)              // 5120 halves
#define GB_ST (32 * GBLDH)               // 4352 halves
#define GST (GA_ST + GB_ST)              // 9472 halves/stage
#define GSTG 3
#define GCLD 132
#define GSMEM_BYTES (128 * GCLD * 4)     // 67584 >= 3*GST*2=56832

template <bool OUTH>
__global__ void __launch_bounds__(256, 2) gemm_h(
    const __half* __restrict__ A, const __half* __restrict__ B,
    void* __restrict__ Cout, int M, int N, int K)
{
    extern __shared__ __align__(16) unsigned char smraw[];
    __half* smh = (__half*)smraw;
    float* smf = (float*)smraw;

    const int tid = threadIdx.x;
    const int w = tid >> 5;
    const int wm = w & 3;
    const int wn = w >> 2;
    const int bx = blockIdx.x;
    const int by = blockIdx.y;

    const __half* Ab = A + (size_t)by * 128 * K;
    const __half* Bb = B + (size_t)bx * 128;
    const int nK = K >> 5;

    auto loadStage = [&](int s, int kt) {
        __half* As = smh + s * GST;
        __half* Bs = As + GA_ST;
#pragma unroll
        for (int i = 0; i < 2; i++) {
            int idx = tid + i * 256;
            int r = idx >> 2, c8 = (idx & 3) << 3;
            cp_async16(&As[r * GALDH + c8], Ab + (size_t)r * K + kt + c8);
        }
#pragma unroll
        for (int i = 0; i < 2; i++) {
            int idx = tid + i * 256;
            int r = idx >> 4, c8 = (idx & 15) << 3;
            cp_async16(&Bs[r * GBLDH + c8], Bb + (size_t)(kt + r) * N + c8);
        }
        cp_commit();
    };

    HC acc[2][4];
#pragma unroll
    for (int i = 0; i < 2; i++)
#pragma unroll
        for (int j = 0; j < 4; j++) wmma::fill_fragment(acc[i][j], 0.f);

    loadStage(0, 0);
    loadStage(1, 32);

    for (int kt = 0; kt < nK; kt++) {
        cp_wait<1>();
        __syncthreads();
        if (kt + 2 < nK) loadStage((kt + 2) % GSTG, (kt + 2) << 5);
        else cp_commit();   // empty group keeps wait<1> semantics exact

        __half* As = smh + (kt % GSTG) * GST;
        __half* Bs = As + GA_ST;
#pragma unroll
        for (int ks = 0; ks < 32; ks += 16) {
            HA af[2];
            HBR bf[4];
#pragma unroll
            for (int i = 0; i < 2; i++)
                wmma::load_matrix_sync(af[i], &As[(wm * 32 + i * 16) * GALDH + ks], GALDH);
#pragma unroll
            for (int j = 0; j < 4; j++)
                wmma::load_matrix_sync(bf[j], &Bs[ks * GBLDH + wn * 64 + j * 16], GBLDH);
#pragma unroll
            for (int i = 0; i < 2; i++)
#pragma unroll
                for (int j = 0; j < 4; j++)
                    wmma::mma_sync(acc[i][j], af[i], bf[j], acc[i][j]);
        }
    }

    cp_wait<0>();
    __syncthreads();   // pipeline dead; reuse smem as fp32 C staging
#pragma unroll
    for (int i = 0; i < 2; i++)
#pragma unroll
        for (int j = 0; j < 4; j++)
            wmma::store_matrix_sync(&smf[(wm * 32 + i * 16) * GCLD + wn * 64 + j * 16],
                                    acc[i][j], GCLD, wmma::mem_row_major);
    __syncthreads();

    if (OUTH) {
        __half* C = (__half*)Cout;
#pragma unroll
        for (int it = 0; it < 16; it++) {
            int idx = tid + it * 256;          // 0..4095
            int r = idx >> 5, c4 = (idx & 31) << 2;
            float4 v = *(const float4*)&smf[r * GCLD + c4];
            __half2 h0 = __floats2half2_rn(v.x, v.y);
            __half2 h1 = __floats2half2_rn(v.z, v.w);
            uint2 u = make_uint2(*(unsigned*)&h0, *(unsigned*)&h1);
            *(uint2*)(C + (size_t)(by * 128 + r) * N + bx * 128 + c4) = u;
        }
    } else {
        float* C = (float*)Cout;
#pragma unroll
        for (int it = 0; it < 16; it++) {
            int idx = tid + it * 256;
            int r = idx >> 5, c4 = (idx & 31) << 2;
            float4 v = *(const float4*)&smf[r * GCLD + c4];
            *(float4*)(C + (size_t)(by * 128 + r) * N + bx * 128 + c4) = v;
        }
    }
}

// ---------------------------------------------------------------------------
// Output learned mask (float4, in place on d_out)
// ---------------------------------------------------------------------------
__global__ void mask_kernel(float4* __restrict__ out,
                            const float* __restrict__ A2,
                            const float* __restrict__ B2, int total4)
{
    int idx = blockIdx.x * 256 + threadIdx.x;
    if (idx >= total4) return;
    int col = (idx & (CC / 4 - 1)) << 2;
    float4 v = out[idx];
    v.x *= cosmask(fmaf(A2[col + 0], v.x, B2[col + 0]));
    v.y *= cosmask(fmaf(A2[col + 1], v.y, B2[col + 1]));
    v.z *= cosmask(fmaf(A2[col + 2], v.z, B2[col + 2]));
    v.w *= cosmask(fmaf(A2[col + 3], v.w, B2[col + 3]));
    out[idx] = v;
}

// ---------------------------------------------------------------------------
// S->E (fp16 inputs): one CTA per causal 128x128 tile. grid (136,H,B).
// Q already pre-scaled by 1/8. E stored fp32.
// Smem: Qs/Ks half 128x72 each (36.9KB) overlapped by fp32 Sbuf 128x132 (67.6KB).
// ---------------------------------------------------------------------------
#define SQLD 72
#define SSLD 132
#define S2E_SMEM (128 * SSLD * 4)   // 67584 bytes

__global__ void __launch_bounds__(256, 2) s2e_h(
    const __half* __restrict__ qkvh, float* __restrict__ E)
{
    extern __shared__ __align__(16) unsigned char smraw[];
    __half* Qs = (__half*)smraw;
    __half* Ks = Qs + 128 * SQLD;
    float* Sbuf = (float*)smraw;

    const int p = blockIdx.x;
    const int h = blockIdx.y;
    const int b = blockIdx.z;
    int qt = 0;
    while ((qt + 1) * (qt + 2) / 2 <= p) qt++;
    const int kt = p - qt * (qt + 1) / 2;

    const int tid = threadIdx.x;
    const int w = tid >> 5;
    const int wm = w & 3;
    const int wn = w >> 2;
    const size_t bOff = (size_t)b * TT * 3 * CC;
    const int ldq = 3 * CC;
    const int hOff = h * HD;
    const size_t eB = ((size_t)(b * HH + h) * TT + (size_t)qt * 128) * TT + (size_t)kt * 128;

#pragma unroll
    for (int i = 0; i < 4; i++) {
        int idx = tid + i * 256;          // 0..1023
        int r = idx >> 3, c8 = (idx & 7) << 3;
        *(uint4*)&Qs[r * SQLD + c8] =
            *(const uint4*)(qkvh + bOff + (size_t)(qt * 128 + r) * ldq + hOff + c8);
        *(uint4*)&Ks[r * SQLD + c8] =
            *(const uint4*)(qkvh + bOff + (size_t)(kt * 128 + r) * ldq + CC + hOff + c8);
    }
    __syncthreads();

    HC sacc[2][4];
#pragma unroll
    for (int i = 0; i < 2; i++)
#pragma unroll
        for (int j = 0; j < 4; j++) wmma::fill_fragment(sacc[i][j], 0.f);

#pragma unroll
    for (int ks = 0; ks < 64; ks += 16) {
        HA af[2];
        HBC bf[4];
#pragma unroll
        for (int i = 0; i < 2; i++)
            wmma::load_matrix_sync(af[i], &Qs[(wm * 32 + i * 16) * SQLD + ks], SQLD);
#pragma unroll
        for (int j = 0; j < 4; j++)
            wmma::load_matrix_sync(bf[j], &Ks[(wn * 64 + j * 16) * SQLD + ks], SQLD);
#pragma unroll
        for (int i = 0; i < 2; i++)
#pragma unroll
            for (int j = 0; j < 4; j++)
                wmma::mma_sync(sacc[i][j], af[i], bf[j], sacc[i][j]);
    }

    if (kt < qt) {
        // off-diagonal: exp in fragments, straight to gmem E
#pragma unroll
        for (int i = 0; i < 2; i++)
#pragma unroll
            for (int j = 0; j < 4; j++) {
#pragma unroll
                for (int e = 0; e < sacc[i][j].num_elements; e++)
                    sacc[i][j].x[e] = __expf(fminf(sacc[i][j].x[e], 60.f));
                wmma::store_matrix_sync(
                    E + eB + (size_t)(wm * 32 + i * 16) * TT + wn * 64 + j * 16,
                    sacc[i][j], TT, wmma::mem_row_major);
            }
    } else {
        // diagonal: stage fp32, causal zero + exp, write
        __syncthreads();   // Qs/Ks dead; Sbuf may overwrite
#pragma unroll
        for (int i = 0; i < 2; i++)
#pragma unroll
            for (int j = 0; j < 4; j++)
                wmma::store_matrix_sync(&Sbuf[(wm * 32 + i * 16) * SSLD + wn * 64 + j * 16],
                                        sacc[i][j], SSLD, wmma::mem_row_major);
        __syncthreads();
#pragma unroll
        for (int i = 0; i < 16; i++) {
            int r = (tid >> 5) + i * 8;
            int c = (tid & 31) << 2;
            float4 s4 = *(const float4*)&Sbuf[r * SSLD + c];
            float4 e4;
            e4.x = (c + 0 <= r) ? __expf(fminf(s4.x, 60.f)) : 0.f;
            e4.y = (c + 1 <= r) ? __expf(fminf(s4.y, 60.f)) : 0.f;
            e4.z = (c + 2 <= r) ? __expf(fminf(s4.z, 60.f)) : 0.f;
            e4.w = (c + 3 <= r) ? __expf(fminf(s4.w, 60.f)) : 0.f;
            *(float4*)(E + eB + (size_t)r * TT + c) = e4;
        }
    }
}

// ---------------------------------------------------------------------------
// Row sums of E -> 1/l. One warp per row. (unchanged)
// ---------------------------------------------------------------------------
__global__ void rowsum_kernel(const float* __restrict__ E, float* __restrict__ L)
{
    const int R = blockIdx.x * 8 + (threadIdx.x >> 5);
    const int lane = threadIdx.x & 31;
    const int r = R & (TT - 1);
    const int bh = R >> 11;
    const int len = ((r >> 7) + 1) << 7;
    const float* row = E + ((size_t)bh * TT + r) * TT;
    float s = 0.f;
    for (int k = lane * 4; k < len; k += 128) {
        float4 v = *(const float4*)(row + k);
        s += (v.x + v.y) + (v.z + v.w);
    }
#pragma unroll
    for (int o = 16; o > 0; o >>= 1) s += __shfl_xor_sync(0xffffffffu, s, o);
    if (lane == 0) L[R] = 1.f / s;
}

// ---------------------------------------------------------------------------
// PV (fp16): per (qt,h,b) CTA. O[128x64] = sum_kt P'(128x128) V(128x64).
// P' = (E/l)*cosmask fused at E load, staged as half. Output att in half.
// Smem: Ps half 128x136 (34.8KB, reused as fp32 O 128x68) + Vs half 128x72
// (18.4KB) + ls (0.5KB) = 53.8KB.
// ---------------------------------------------------------------------------
#define PLD 136
#define PVLD 72
#define PV_LS_BYTE (128 * PLD * 2 + 128 * PVLD * 2)   // 53248
#define PV_SMEM (PV_LS_BYTE + 128 * 4)                // 53760

__global__ void __launch_bounds__(256, 2) pv_h(
    const __half* __restrict__ qkvh, const float* __restrict__ E,
    const float* __restrict__ L,
    const float* __restrict__ A1, const float* __restrict__ B1,
    __half* __restrict__ atth)
{
    extern __shared__ __align__(16) unsigned char smraw[];
    __half* Ps = (__half*)smraw;
    __half* Vs = Ps + 128 * PLD;
    float* ls = (float*)(smraw + PV_LS_BYTE);
    float* Obuf = (float*)smraw;       // reused after mainloop (128x68 fp32)

    const int tid = threadIdx.x;
    const int w = tid >> 5;
    const int wm = w & 3;
    const int wn = w >> 2;
    const int qt = (gridDim.x - 1) - blockIdx.x;   // heavy first
    const int h = blockIdx.y;
    const int b = blockIdx.z;
    const int bh = b * HH + h;
    const size_t bOff = (size_t)b * TT * 3 * CC;
    const int ldq = 3 * CC;
    const int hOff = h * HD;
    const size_t eQ = ((size_t)bh * TT + (size_t)qt * 128) * TT;

    if (tid < 128) ls[tid] = L[bh * TT + qt * 128 + tid];
    __syncthreads();

    HC oacc[2][2];
#pragma unroll
    for (int i = 0; i < 2; i++)
#pragma unroll
        for (int t = 0; t < 2; t++) wmma::fill_fragment(oacc[i][t], 0.f);

    for (int kt = 0; kt <= qt; kt++) {
        const int kBase = kt * 128;
        // V tile [128][64] half
#pragma unroll
        for (int i = 0; i < 4; i++) {
            int idx = tid + i * 256;
            int r = idx >> 3, c8 = (idx & 7) << 3;
            *(uint4*)&Vs[r * PVLD + c8] =
                *(const uint4*)(qkvh + bOff + (size_t)(kBase + r) * ldq + 2 * CC + hOff + c8);
        }
        // E -> P' (half staged)
#pragma unroll
        for (int i = 0; i < 16; i++) {
            int r = (tid >> 5) + i * 8;
            int c = (tid & 31) << 2;
            float4 e4 = *(const float4*)(E + eQ + (size_t)r * TT + kBase + c);
            float rl = ls[r];
            int k0 = kBase + c;
            float4 p4;
            p4.x = e4.x * rl; p4.y = e4.y * rl;
            p4.z = e4.z * rl; p4.w = e4.w * rl;
            p4.x *= cosmask(fmaf(__ldg(A1 + k0 + 0), p4.x, __ldg(B1 + k0 + 0)));
            p4.y *= cosmask(fmaf(__ldg(A1 + k0 + 1), p4.y, __ldg(B1 + k0 + 1)));
            p4.z *= cosmask(fmaf(__ldg(A1 + k0 + 2), p4.z, __ldg(B1 + k0 + 2)));
            p4.w *= cosmask(fmaf(__ldg(A1 + k0 + 3), p4.w, __ldg(B1 + k0 + 3)));
            __half2 h0 = __floats2half2_rn(p4.x, p4.y);
            __half2 h1 = __floats2half2_rn(p4.z, p4.w);
            uint2 u = make_uint2(*(unsigned*)&h0, *(unsigned*)&h1);
            *(uint2*)&Ps[r * PLD + c] = u;
        }
        __syncthreads();

#pragma unroll
        for (int ks = 0; ks < 128; ks += 16) {
            HA af[2];
#pragma unroll
            for (int i = 0; i < 2; i++)
                wmma::load_matrix_sync(af[i], &Ps[(wm * 32 + i * 16) * PLD + ks], PLD);
#pragma unroll
            for (int t = 0; t < 2; t++) {
                HBR bf;
                wmma::load_matrix_sync(bf, &Vs[ks * PVLD + wn * 32 + t * 16], PVLD);
#pragma unroll
                for (int i = 0; i < 2; i++)
                    wmma::mma_sync(oacc[i][t], af[i], bf, oacc[i][t]);
            }
        }
        __syncthreads();
    }

    // epilogue: stage fp32 O, convert to half att
#pragma unroll
    for (int i = 0; i < 2; i++)
#pragma unroll
        for (int t = 0; t < 2; t++)
            wmma::store_matrix_sync(&Obuf[(wm * 32 + i * 16) * 68 + wn * 32 + t * 16],
                                    oacc[i][t], 68, wmma::mem_row_major);
    __syncthreads();

    const size_t oBase = (size_t)b * TT * CC + (size_t)qt * 128 * CC + hOff;
#pragma unroll
    for (int it = 0; it < 8; it++) {
        int idx = tid + it * 256;          // 0..2047
        int r = idx >> 4, c4 = (idx & 15) << 2;
        float4 v = *(const float4*)&Obuf[r * 68 + c4];
        __half2 h0 = __floats2half2_rn(v.x, v.y);
        __half2 h1 = __floats2half2_rn(v.z, v.w);
        uint2 u = make_uint2(*(unsigned*)&h0, *(unsigned*)&h1);
        *(uint2*)(atth + oBase + (size_t)r * CC + c4) = u;
    }
}

// ---------------------------------------------------------------------------
extern "C" void kernel_launch(void* const* d_in, const int* in_sizes, int n_in,
                              void* d_out, int out_size)
{
    const float* x     = (const float*)d_in[0];
    const float* Wqkv  = (const float*)d_in[1];
    const float* Wproj = (const float*)d_in[2];
    const float* A1    = (const float*)d_in[3];
    const float* B1    = (const float*)d_in[4];
    const float* A2    = (const float*)d_in[5];
    const float* B2    = (const float*)d_in[6];
    float* out = (float*)d_out;

    __half *xh, *wqkvh, *wprojh, *qkvh, *atth;
    float *E, *L;
    cudaGetSymbolAddress((void**)&xh, g_xh);
    cudaGetSymbolAddress((void**)&wqkvh, g_wqkvh);
    cudaGetSymbolAddress((void**)&wprojh, g_wprojh);
    cudaGetSymbolAddress((void**)&qkvh, g_qkvh);
    cudaGetSymbolAddress((void**)&atth, g_atth);
    cudaGetSymbolAddress((void**)&E, g_e);
    cudaGetSymbolAddress((void**)&L, g_l);

    cudaFuncSetAttribute(gemm_h<true>, cudaFuncAttributeMaxDynamicSharedMemorySize,
                         GSMEM_BYTES);
    cudaFuncSetAttribute(gemm_h<false>, cudaFuncAttributeMaxDynamicSharedMemorySize,
                         GSMEM_BYTES);
    cudaFuncSetAttribute(s2e_h, cudaFuncAttributeMaxDynamicSharedMemorySize, S2E_SMEM);
    cudaFuncSetAttribute(pv_h, cudaFuncAttributeMaxDynamicSharedMemorySize, PV_SMEM);

    // 0) convert inputs to fp16 (Wqkv with Q-scale folded)
    f2h_kernel<<<(BD * TT * CC / 4 + 255) / 256, 256>>>(xh, x, BD * TT * CC / 4);
    wqkv_cvt_kernel<<<(CC * 3 * CC / 4) / 256, 256>>>(wqkvh, Wqkv);
    f2h_kernel<<<(CC * CC / 4 + 255) / 256, 256>>>(wprojh, Wproj, CC * CC / 4);

    // 1) QKV projection (half out): [4096,1024] @ [1024,3072]
    {
        dim3 grid(3 * CC / 128, (BD * TT) / 128);
        gemm_h<true><<<grid, 256, GSMEM_BYTES>>>(xh, wqkvh, qkvh, BD * TT, 3 * CC, CC);
    }
    // 2a) S -> E
    {
        dim3 grid(136, HH, BD);
        s2e_h<<<grid, 256, S2E_SMEM>>>(qkvh, E);
    }
    // 2b) row sums -> 1/l
    rowsum_kernel<<<BD * HH * TT / 8, 256>>>(E, L);
    // 2c) O = P' V (half out)
    {
        dim3 grid(TT / 128, HH, BD);
        pv_h<<<grid, 256, PV_SMEM>>>(qkvh, E, L, A1, B1, atth);
    }
    // 3) output projection (float out): [4096,1024] @ [1024,1024]
    {
        dim3 grid(CC / 128, (BD * TT) / 128);
        gemm_h<false><<<grid, 256, GSMEM_BYTES>>>(atth, wprojh, out, BD * TT, CC, CC);
    }
    // 4) output learned mask
    {
        int total4 = BD * TT * CC / 4;
        mask_kernel<<<(total4 + 255) / 256, 256>>>((float4*)out, A2, B2, total4);
    }
}

// round 14
// speedup vs baseline: 4.0659x; 1.1311x over previous
#include <cuda_runtime.h>
#include <cuda_fp16.h>
#include <mma.h>
#include <math.h>

using namespace nvcuda;

#define BD 2
#define TT 2048
#define CC 1024
#define HH 16
#define HD 64

// Scratch (no cudaMalloc allowed)
__device__ __half g_xh[(size_t)BD * TT * CC];
__device__ __half g_wqkvh[(size_t)CC * 3 * CC];      // Q columns pre-scaled by 1/8
__device__ __half g_wprojh[(size_t)CC * CC];
__device__ __half g_qkvh[(size_t)BD * TT * 3 * CC];  // [B,T,3C], q already /8
__device__ __half g_atth[(size_t)BD * TT * CC];
__device__ __half g_eh[(size_t)BD * HH * TT * TT];   // E = exp(S), fp16
__device__ float  g_lp[(size_t)BD * HH * TT * 16];   // per-(row, ktile) partial sums
__device__ float  g_l[(size_t)BD * HH * TT];         // 1/rowsum

typedef wmma::fragment<wmma::matrix_a, 16, 16, 16, __half, wmma::row_major> HA;
typedef wmma::fragment<wmma::matrix_b, 16, 16, 16, __half, wmma::row_major> HBR;
typedef wmma::fragment<wmma::matrix_b, 16, 16, 16, __half, wmma::col_major> HBC;
typedef wmma::fragment<wmma::accumulator, 16, 16, 16, float> HC;

// 0.5*cos(x)+0.5 = 1 + x2*(-1/4 + x2*(1/48 - x2/1440)); |x| small here
__device__ __forceinline__ float cosmask(float x) {
    float x2 = x * x;
    return fmaf(x2, fmaf(x2, fmaf(x2, -6.9444444e-4f, 2.0833333e-2f), -0.25f), 1.0f);
}

__device__ __forceinline__ void cp_async16(void* smem, const void* gmem) {
    unsigned saddr = (unsigned)__cvta_generic_to_shared(smem);
    asm volatile("cp.async.cg.shared.global [%0], [%1], 16;\n" :: "r"(saddr), "l"(gmem));
}
__device__ __forceinline__ void cp_commit() {
    asm volatile("cp.async.commit_group;\n");
}
template <int N>
__device__ __forceinline__ void cp_wait() {
    asm volatile("cp.async.wait_group %0;\n" :: "n"(N));
}

// ---------------------------------------------------------------------------
// fp32 -> fp16 converters
// ---------------------------------------------------------------------------
__global__ void f2h_kernel(__half* __restrict__ dst, const float* __restrict__ src, int n4)
{
    int i = blockIdx.x * 256 + threadIdx.x;
    if (i >= n4) return;
    float4 v = ((const float4*)src)[i];
    ((__half2*)dst)[i * 2 + 0] = __floats2half2_rn(v.x, v.y);
    ((__half2*)dst)[i * 2 + 1] = __floats2half2_rn(v.z, v.w);
}

// Wqkv with Q-columns (col < CC) pre-scaled by 1/8
__global__ void wqkv_cvt_kernel(__half* __restrict__ dst, const float* __restrict__ src)
{
    int i = blockIdx.x * 256 + threadIdx.x;   // n4 = CC*3*CC/4, exact grid
    float4 v = ((const float4*)src)[i];
    int col = (i * 4) % (3 * CC);
    float s = (col < CC) ? 0.125f : 1.f;
    ((__half2*)dst)[i * 2 + 0] = __floats2half2_rn(v.x * s, v.y * s);
    ((__half2*)dst)[i * 2 + 1] = __floats2half2_rn(v.z * s, v.w * s);
}

// ---------------------------------------------------------------------------
// fp16 GEMM, fp32 accum: C[M,N] = A[M,K] @ B[K,N]. BM=BN=128, BK=32,
// 3-stage cp.async pipeline, 8 warps, warp tile 32x64.
// OUTH: half output. MASK: fused learned mask (float output path only).
// ---------------------------------------------------------------------------
#define GALDH 40      // A pad (32+8 halves)
#define GBLDH 136     // B pad (128+8 halves)
#define GA_ST (128 * GALDH)
#define GB_ST (32 * GBLDH)
#define GST (GA_ST + GB_ST)
#define GSTG 3
#define GCLD 132
#define GSMEM_BYTES (128 * GCLD * 4)     // 67584 >= 3*GST*2=56832

template <bool OUTH, bool MASK>
__global__ void __launch_bounds__(256, 2) gemm_h(
    const __half* __restrict__ A, const __half* __restrict__ B,
    void* __restrict__ Cout, int M, int N, int K,
    const float* __restrict__ MA, const float* __restrict__ MB)
{
    extern __shared__ __align__(16) unsigned char smraw[];
    __half* smh = (__half*)smraw;
    float* smf = (float*)smraw;

    const int tid = threadIdx.x;
    const int w = tid >> 5;
    const int wm = w & 3;
    const int wn = w >> 2;
    const int bx = blockIdx.x;
    const int by = blockIdx.y;

    const __half* Ab = A + (size_t)by * 128 * K;
    const __half* Bb = B + (size_t)bx * 128;
    const int nK = K >> 5;

    auto loadStage = [&](int s, int kt) {
        __half* As = smh + s * GST;
        __half* Bs = As + GA_ST;
#pragma unroll
        for (int i = 0; i < 2; i++) {
            int idx = tid + i * 256;
            int r = idx >> 2, c8 = (idx & 3) << 3;
            cp_async16(&As[r * GALDH + c8], Ab + (size_t)r * K + kt + c8);
        }
#pragma unroll
        for (int i = 0; i < 2; i++) {
            int idx = tid + i * 256;
            int r = idx >> 4, c8 = (idx & 15) << 3;
            cp_async16(&Bs[r * GBLDH + c8], Bb + (size_t)(kt + r) * N + c8);
        }
        cp_commit();
    };

    HC acc[2][4];
#pragma unroll
    for (int i = 0; i < 2; i++)
#pragma unroll
        for (int j = 0; j < 4; j++) wmma::fill_fragment(acc[i][j], 0.f);

    loadStage(0, 0);
    loadStage(1, 32);

    for (int kt = 0; kt < nK; kt++) {
        cp_wait<1>();
        __syncthreads();
        if (kt + 2 < nK) loadStage((kt + 2) % GSTG, (kt + 2) << 5);
        else cp_commit();   // empty group keeps wait<1> semantics exact

        __half* As = smh + (kt % GSTG) * GST;
        __half* Bs = As + GA_ST;
#pragma unroll
        for (int ks = 0; ks < 32; ks += 16) {
            HA af[2];
            HBR bf[4];
#pragma unroll
            for (int i = 0; i < 2; i++)
                wmma::load_matrix_sync(af[i], &As[(wm * 32 + i * 16) * GALDH + ks], GALDH);
#pragma unroll
            for (int j = 0; j < 4; j++)
                wmma::load_matrix_sync(bf[j], &Bs[ks * GBLDH + wn * 64 + j * 16], GBLDH);
#pragma unroll
            for (int i = 0; i < 2; i++)
#pragma unroll
                for (int j = 0; j < 4; j++)
                    wmma::mma_sync(acc[i][j], af[i], bf[j], acc[i][j]);
        }
    }

    cp_wait<0>();
    __syncthreads();   // pipeline dead; reuse smem as fp32 C staging
#pragma unroll
    for (int i = 0; i < 2; i++)
#pragma unroll
        for (int j = 0; j < 4; j++)
            wmma::store_matrix_sync(&smf[(wm * 32 + i * 16) * GCLD + wn * 64 + j * 16],
                                    acc[i][j], GCLD, wmma::mem_row_major);
    __syncthreads();

    if (OUTH) {
        __half* C = (__half*)Cout;
#pragma unroll
        for (int it = 0; it < 16; it++) {
            int idx = tid + it * 256;
            int r = idx >> 5, c4 = (idx & 31) << 2;
            float4 v = *(const float4*)&smf[r * GCLD + c4];
            __half2 h0 = __floats2half2_rn(v.x, v.y);
            __half2 h1 = __floats2half2_rn(v.z, v.w);
            uint2 u = make_uint2(*(unsigned*)&h0, *(unsigned*)&h1);
            *(uint2*)(C + (size_t)(by * 128 + r) * N + bx * 128 + c4) = u;
        }
    } else {
        float* C = (float*)Cout;
#pragma unroll
        for (int it = 0; it < 16; it++) {
            int idx = tid + it * 256;
            int r = idx >> 5, c4 = (idx & 31) << 2;
            float4 v = *(const float4*)&smf[r * GCLD + c4];
            if (MASK) {
                int col = bx * 128 + c4;
                v.x *= cosmask(fmaf(__ldg(MA + col + 0), v.x, __ldg(MB + col + 0)));
                v.y *= cosmask(fmaf(__ldg(MA + col + 1), v.y, __ldg(MB + col + 1)));
                v.z *= cosmask(fmaf(__ldg(MA + col + 2), v.z, __ldg(MB + col + 2)));
                v.w *= cosmask(fmaf(__ldg(MA + col + 3), v.w, __ldg(MB + col + 3)));
            }
            *(float4*)(C + (size_t)(by * 128 + r) * N + bx * 128 + c4) = v;
        }
    }
}

// ---------------------------------------------------------------------------
// S->E (fp16): one CTA per causal 128x128 tile. grid (136,H,B).
// Q pre-scaled by 1/8. E stored fp16. Per-tile row sums (fp32, from staged S)
// written to Lp[(bh*TT + row) * 16 + kt] — no atomics, deterministic.
// Smem: Qs/Ks half 128x72 (36.9KB) overlapped by fp32 Sbuf 128x132 (67.6KB).
// ---------------------------------------------------------------------------
#define SQLD 72
#define SSLD 132
#define S2E_SMEM (128 * SSLD * 4)

__global__ void __launch_bounds__(256, 2) s2e_h(
    const __half* __restrict__ qkvh, __half* __restrict__ E,
    float* __restrict__ Lp)
{
    extern __shared__ __align__(16) unsigned char smraw[];
    __half* Qs = (__half*)smraw;
    __half* Ks = Qs + 128 * SQLD;
    float* Sbuf = (float*)smraw;

    const int p = blockIdx.x;
    const int h = blockIdx.y;
    const int b = blockIdx.z;
    int qt = 0;
    while ((qt + 1) * (qt + 2) / 2 <= p) qt++;
    const int kt = p - qt * (qt + 1) / 2;

    const int tid = threadIdx.x;
    const int w = tid >> 5;
    const int wm = w & 3;
    const int wn = w >> 2;
    const int lane = tid & 31;
    const size_t bOff = (size_t)b * TT * 3 * CC;
    const int ldq = 3 * CC;
    const int hOff = h * HD;
    const int bh = b * HH + h;
    const size_t eB = ((size_t)bh * TT + (size_t)qt * 128) * TT + (size_t)kt * 128;
    const bool diag = (kt == qt);

#pragma unroll
    for (int i = 0; i < 4; i++) {
        int idx = tid + i * 256;
        int r = idx >> 3, c8 = (idx & 7) << 3;
        *(uint4*)&Qs[r * SQLD + c8] =
            *(const uint4*)(qkvh + bOff + (size_t)(qt * 128 + r) * ldq + hOff + c8);
        *(uint4*)&Ks[r * SQLD + c8] =
            *(const uint4*)(qkvh + bOff + (size_t)(kt * 128 + r) * ldq + CC + hOff + c8);
    }
    __syncthreads();

    HC sacc[2][4];
#pragma unroll
    for (int i = 0; i < 2; i++)
#pragma unroll
        for (int j = 0; j < 4; j++) wmma::fill_fragment(sacc[i][j], 0.f);

#pragma unroll
    for (int ks = 0; ks < 64; ks += 16) {
        HA af[2];
        HBC bf[4];
#pragma unroll
        for (int i = 0; i < 2; i++)
            wmma::load_matrix_sync(af[i], &Qs[(wm * 32 + i * 16) * SQLD + ks], SQLD);
#pragma unroll
        for (int j = 0; j < 4; j++)
            wmma::load_matrix_sync(bf[j], &Ks[(wn * 64 + j * 16) * SQLD + ks], SQLD);
#pragma unroll
        for (int i = 0; i < 2; i++)
#pragma unroll
            for (int j = 0; j < 4; j++)
                wmma::mma_sync(sacc[i][j], af[i], bf[j], sacc[i][j]);
    }

    __syncthreads();   // Qs/Ks dead; Sbuf may overwrite
#pragma unroll
    for (int i = 0; i < 2; i++)
#pragma unroll
        for (int j = 0; j < 4; j++)
            wmma::store_matrix_sync(&Sbuf[(wm * 32 + i * 16) * SSLD + wn * 64 + j * 16],
                                    sacc[i][j], SSLD, wmma::mem_row_major);
    __syncthreads();

    // exp + (diag causal zero) + E(half) write + per-row warp sums -> Lp
#pragma unroll
    for (int i = 0; i < 16; i++) {
        int r = w + i * 8;                 // warp w handles rows w, w+8, ...
        int c = lane << 2;
        float4 s4 = *(const float4*)&Sbuf[r * SSLD + c];
        float4 e4;
        if (diag) {
            e4.x = (c + 0 <= r) ? __expf(fminf(s4.x, 60.f)) : 0.f;
            e4.y = (c + 1 <= r) ? __expf(fminf(s4.y, 60.f)) : 0.f;
            e4.z = (c + 2 <= r) ? __expf(fminf(s4.z, 60.f)) : 0.f;
            e4.w = (c + 3 <= r) ? __expf(fminf(s4.w, 60.f)) : 0.f;
        } else {
            e4.x = __expf(fminf(s4.x, 60.f));
            e4.y = __expf(fminf(s4.y, 60.f));
            e4.z = __expf(fminf(s4.z, 60.f));
            e4.w = __expf(fminf(s4.w, 60.f));
        }
        __half2 h0 = __floats2half2_rn(e4.x, e4.y);
        __half2 h1 = __floats2half2_rn(e4.z, e4.w);
        uint2 u = make_uint2(*(unsigned*)&h0, *(unsigned*)&h1);
        *(uint2*)(E + eB + (size_t)r * TT + c) = u;

        float s = (e4.x + e4.y) + (e4.z + e4.w);
#pragma unroll
        for (int o = 16; o > 0; o >>= 1) s += __shfl_xor_sync(0xffffffffu, s, o);
        if (lane == 0)
            Lp[((size_t)bh * TT + qt * 128 + r) * 16 + kt] = s;
    }
}

// ---------------------------------------------------------------------------
// Reciprocal of row sums: L[row] = 1 / sum_kt Lp[row][kt]. Deterministic.
// ---------------------------------------------------------------------------
__global__ void recip_kernel(const float* __restrict__ Lp, float* __restrict__ L, int n)
{
    int i = blockIdx.x * 256 + threadIdx.x;
    if (i >= n) return;
    int r = i & (TT - 1);
    int nk = (r >> 7) + 1;
    const float* p = Lp + (size_t)i * 16;
    float s = 0.f;
    for (int k = 0; k < nk; k++) s += p[k];
    L[i] = 1.f / s;
}

// ---------------------------------------------------------------------------
// PV (fp16): per (qt,h,b) CTA. O[128x64] = sum_kt P'(128x128) V(128x64).
// P' = (E/l)*cosmask fused at (half) E load, staged as half.
// ---------------------------------------------------------------------------
#define PLD 136
#define PVLD 72
#define PV_LS_BYTE (128 * PLD * 2 + 128 * PVLD * 2)
#define PV_SMEM (PV_LS_BYTE + 128 * 4)

__global__ void __launch_bounds__(256, 2) pv_h(
    const __half* __restrict__ qkvh, const __half* __restrict__ E,
    const float* __restrict__ L,
    const float* __restrict__ A1, const float* __restrict__ B1,
    __half* __restrict__ atth)
{
    extern __shared__ __align__(16) unsigned char smraw[];
    __half* Ps = (__half*)smraw;
    __half* Vs = Ps + 128 * PLD;
    float* ls = (float*)(smraw + PV_LS_BYTE);
    float* Obuf = (float*)smraw;       // reused after mainloop (128x68 fp32)

    const int tid = threadIdx.x;
    const int w = tid >> 5;
    const int wm = w & 3;
    const int wn = w >> 2;
    const int qt = (gridDim.x - 1) - blockIdx.x;   // heavy first
    const int h = blockIdx.y;
    const int b = blockIdx.z;
    const int bh = b * HH + h;
    const size_t bOff = (size_t)b * TT * 3 * CC;
    const int ldq = 3 * CC;
    const int hOff = h * HD;
    const size_t eQ = ((size_t)bh * TT + (size_t)qt * 128) * TT;

    if (tid < 128) ls[tid] = L[bh * TT + qt * 128 + tid];
    __syncthreads();

    HC oacc[2][2];
#pragma unroll
    for (int i = 0; i < 2; i++)
#pragma unroll
        for (int t = 0; t < 2; t++) wmma::fill_fragment(oacc[i][t], 0.f);

    for (int kt = 0; kt <= qt; kt++) {
        const int kBase = kt * 128;
#pragma unroll
        for (int i = 0; i < 4; i++) {
            int idx = tid + i * 256;
            int r = idx >> 3, c8 = (idx & 7) << 3;
            *(uint4*)&Vs[r * PVLD + c8] =
                *(const uint4*)(qkvh + bOff + (size_t)(kBase + r) * ldq + 2 * CC + hOff + c8);
        }
        // E(half) -> P' (half staged)
#pragma unroll
        for (int i = 0; i < 16; i++) {
            int r = w + i * 8;
            int c = (tid & 31) << 2;
            uint2 ue = *(const uint2*)(E + eQ + (size_t)r * TT + kBase + c);
            float2 f0 = __half22float2(*(__half2*)&ue.x);
            float2 f1 = __half22float2(*(__half2*)&ue.y);
            float rl = ls[r];
            int k0 = kBase + c;
            float4 p4;
            p4.x = f0.x * rl; p4.y = f0.y * rl;
            p4.z = f1.x * rl; p4.w = f1.y * rl;
            p4.x *= cosmask(fmaf(__ldg(A1 + k0 + 0), p4.x, __ldg(B1 + k0 + 0)));
            p4.y *= cosmask(fmaf(__ldg(A1 + k0 + 1), p4.y, __ldg(B1 + k0 + 1)));
            p4.z *= cosmask(fmaf(__ldg(A1 + k0 + 2), p4.z, __ldg(B1 + k0 + 2)));
            p4.w *= cosmask(fmaf(__ldg(A1 + k0 + 3), p4.w, __ldg(B1 + k0 + 3)));
            __half2 h0 = __floats2half2_rn(p4.x, p4.y);
            __half2 h1 = __floats2half2_rn(p4.z, p4.w);
            uint2 u = make_uint2(*(unsigned*)&h0, *(unsigned*)&h1);
            *(uint2*)&Ps[r * PLD + c] = u;
        }
        __syncthreads();

#pragma unroll
        for (int ks = 0; ks < 128; ks += 16) {
            HA af[2];
#pragma unroll
            for (int i = 0; i < 2; i++)
                wmma::load_matrix_sync(af[i], &Ps[(wm * 32 + i * 16) * PLD + ks], PLD);
#pragma unroll
            for (int t = 0; t < 2; t++) {
                HBR bf;
                wmma::load_matrix_sync(bf, &Vs[ks * PVLD + wn * 32 + t * 16], PVLD);
#pragma unroll
                for (int i = 0; i < 2; i++)
                    wmma::mma_sync(oacc[i][t], af[i], bf, oacc[i][t]);
            }
        }
        __syncthreads();
    }

    // epilogue: stage fp32 O, convert to half att
#pragma unroll
    for (int i = 0; i < 2; i++)
#pragma unroll
        for (int t = 0; t < 2; t++)
            wmma::store_matrix_sync(&Obuf[(wm * 32 + i * 16) * 68 + wn * 32 + t * 16],
                                    oacc[i][t], 68, wmma::mem_row_major);
    __syncthreads();

    const size_t oBase = (size_t)b * TT * CC + (size_t)qt * 128 * CC + hOff;
#pragma unroll
    for (int it = 0; it < 8; it++) {
        int idx = tid + it * 256;
        int r = idx >> 4, c4 = (idx & 15) << 2;
        float4 v = *(const float4*)&Obuf[r * 68 + c4];
        __half2 h0 = __floats2half2_rn(v.x, v.y);
        __half2 h1 = __floats2half2_rn(v.z, v.w);
        uint2 u = make_uint2(*(unsigned*)&h0, *(unsigned*)&h1);
        *(uint2*)(atth + oBase + (size_t)r * CC + c4) = u;
    }
}

// ---------------------------------------------------------------------------
extern "C" void kernel_launch(void* const* d_in, const int* in_sizes, int n_in,
                              void* d_out, int out_size)
{
    const float* x     = (const float*)d_in[0];
    const float* Wqkv  = (const float*)d_in[1];
    const float* Wproj = (const float*)d_in[2];
    const float* A1    = (const float*)d_in[3];
    const float* B1    = (const float*)d_in[4];
    const float* A2    = (const float*)d_in[5];
    const float* B2    = (const float*)d_in[6];
    float* out = (float*)d_out;

    __half *xh, *wqkvh, *wprojh, *qkvh, *atth, *E;
    float *Lp, *L;
    cudaGetSymbolAddress((void**)&xh, g_xh);
    cudaGetSymbolAddress((void**)&wqkvh, g_wqkvh);
    cudaGetSymbolAddress((void**)&wprojh, g_wprojh);
    cudaGetSymbolAddress((void**)&qkvh, g_qkvh);
    cudaGetSymbolAddress((void**)&atth, g_atth);
    cudaGetSymbolAddress((void**)&E, g_eh);
    cudaGetSymbolAddress((void**)&Lp, g_lp);
    cudaGetSymbolAddress((void**)&L, g_l);

    cudaFuncSetAttribute((const void*)gemm_h<true, false>,
                         cudaFuncAttributeMaxDynamicSharedMemorySize, GSMEM_BYTES);
    cudaFuncSetAttribute((const void*)gemm_h<false, true>,
                         cudaFuncAttributeMaxDynamicSharedMemorySize, GSMEM_BYTES);
    cudaFuncSetAttribute((const void*)s2e_h,
                         cudaFuncAttributeMaxDynamicSharedMemorySize, S2E_SMEM);
    cudaFuncSetAttribute((const void*)pv_h,
                         cudaFuncAttributeMaxDynamicSharedMemorySize, PV_SMEM);

    // 0) convert inputs to fp16 (Wqkv with Q-scale folded)
    f2h_kernel<<<(BD * TT * CC / 4 + 255) / 256, 256>>>(xh, x, BD * TT * CC / 4);
    wqkv_cvt_kernel<<<(CC * 3 * CC / 4) / 256, 256>>>(wqkvh, Wqkv);
    f2h_kernel<<<(CC * CC / 4 + 255) / 256, 256>>>(wprojh, Wproj, CC * CC / 4);

    // 1) QKV projection (half out): [4096,1024] @ [1024,3072]
    {
        dim3 grid(3 * CC / 128, (BD * TT) / 128);
        gemm_h<true, false><<<grid, 256, GSMEM_BYTES>>>(
            xh, wqkvh, qkvh, BD * TT, 3 * CC, CC, nullptr, nullptr);
    }
    // 2a) S -> E (half) + partial row sums
    {
        dim3 grid(136, HH, BD);
        s2e_h<<<grid, 256, S2E_SMEM>>>(qkvh, E, Lp);
    }
    // 2b) combine partials -> 1/l
    recip_kernel<<<(BD * HH * TT + 255) / 256, 256>>>(Lp, L, BD * HH * TT);
    // 2c) O = P' V (half out)
    {
        dim3 grid(TT / 128, HH, BD);
        pv_h<<<grid, 256, PV_SMEM>>>(qkvh, E, L, A1, B1, atth);
    }
    // 3) output projection + fused learned mask (float out)
    {
        dim3 grid(CC / 128, (BD * TT) / 128);
        gemm_h<false, true><<<grid, 256, GSMEM_BYTES>>>(
            atth, wprojh, out, BD * TT, CC, CC, A2, B2);
    }
}